// round 1
// baseline (speedup 1.0000x reference)
#include <cuda_runtime.h>
#include <math.h>

#define NN   50000
#define NPAD 50048
#define CCH  96
#define EE   800000
#define NC   (NPAD*CCH)

// ---------------- device scratch (no allocations allowed) ----------------
__device__ float  g_T0[NC];
__device__ float  g_T1[NC];
__device__ float  g_T2[NC];
__device__ float  g_T3[NC];
__device__ float  g_concat[NPAD*288];
__device__ float  g_h[NC];
__device__ float  g_deg[NN];
__device__ float  g_dis[NN];
__device__ float  g_wn[EE];
__device__ int    g_eidx[2*EE];     // decoded int32 row/col
__device__ int    g_is64;
__device__ float  g_Wbig[384*288];
__device__ float  g_bcat[288];
__device__ double g_bnsum[192];     // sums + sumsq
__device__ float  g_bnab[192];      // scale + shift

// ---------------- edge index dtype detect + decode ----------------
__global__ void k_detect(const void* ei) {
    // If int64: every odd 32-bit word (high word) is 0 (indices < 2^31, nonneg).
    // If int32: odd words are random indices in [0,50000) -> essentially never all zero.
    __shared__ int any_nz;
    if (threadIdx.x == 0) any_nz = 0;
    __syncthreads();
    const int* p = (const int*)ei;
    int local = 0;
    for (int i = threadIdx.x; i < 4096; i += 256)
        if (p[2*i + 1] != 0) local = 1;
    if (local) atomicOr(&any_nz, 1);
    __syncthreads();
    if (threadIdx.x == 0) g_is64 = any_nz ? 0 : 1;
}

__global__ void k_decode(const void* ei) {
    int e = blockIdx.x*256 + threadIdx.x;
    if (e >= 2*EE) return;
    int v;
    if (g_is64) v = (int)((const long long*)ei)[e];
    else        v = ((const int*)ei)[e];
    g_eidx[e] = v;
}

// ---------------- prep: T0 = x (padded w/ zeros), T1 = 0, T2 = -T0 ----------------
__global__ void k_prep(const float* __restrict__ x) {
    int i = blockIdx.x*256 + threadIdx.x;
    if (i < NC) {
        float v = (i < NN*CCH) ? x[i] : 0.f;
        g_T0[i] = v; g_T1[i] = 0.f; g_T2[i] = -v;
    }
}

__global__ void k_zero_misc() {
    int i = blockIdx.x*256 + threadIdx.x;
    if (i < NN)  g_deg[i] = 0.f;
    if (i < 192) g_bnsum[i] = 0.0;
}

__global__ void k_deg() {
    int e = blockIdx.x*256 + threadIdx.x;
    if (e < EE) atomicAdd(&g_deg[g_eidx[e]], 1.0f);
}

__global__ void k_dis() {
    int i = blockIdx.x*256 + threadIdx.x;
    if (i < NN) {
        float d = g_deg[i];
        g_dis[i] = (d > 0.f) ? rsqrtf(d) : 0.f;
    }
}

__global__ void k_wn() {
    int e = blockIdx.x*256 + threadIdx.x;
    if (e < EE) {
        int r = g_eidx[e], c = g_eidx[EE + e];
        g_wn[e] = -g_dis[r] * g_dis[c];
    }
}

__global__ void k_negT3() {   // T3 = -T1 (init before prop into T3)
    int i = blockIdx.x*256 + threadIdx.x;
    if (i < NC) g_T3[i] = -g_T1[i];
}

// ---------------- propagation: dst[col] += coef*wn*src[row] ----------------
// 24 threads per edge, one float4 (4 channels) each.
__global__ void k_prop(int which, float coef) {
    const float* src = (which == 0) ? g_T0 : (which == 1) ? g_T1 : g_T2;
    float*       dst = (which == 0) ? g_T1 : (which == 1) ? g_T2 : g_T3;
    int it = blockIdx.x*256 + threadIdx.x;
    if (it >= EE*24) return;
    int e = it / 24;
    int q = it - e*24;
    float w = coef * g_wn[e];
    int r = g_eidx[e];
    int c = g_eidx[EE + e];
    const float4 v = *(const float4*)(src + (size_t)r*CCH + q*4);
    float* d = dst + (size_t)c*CCH + q*4;
    atomicAdd(d + 0, w*v.x);
    atomicAdd(d + 1, w*v.y);
    atomicAdd(d + 2, w*v.z);
    atomicAdd(d + 3, w*v.w);
}

// ---------------- build block-sparse weight [384,288] + bias concat ----------------
__global__ void k_buildW(const float* __restrict__ w2, const float* __restrict__ b2,
                         const float* __restrict__ w3, const float* __restrict__ b3,
                         const float* __restrict__ w4, const float* __restrict__ b4) {
    int idx = blockIdx.x*256 + threadIdx.x;
    if (idx < 384*288) {
        int k = idx / 288, j = idx - k*288;
        int t = k / 96,  ki = k - t*96;
        int f = j / 96,  ji = j - f*96;
        const float* w = (f == 0) ? w2 : (f == 1) ? w3 : w4;
        int Kf = f + 2;   // 2,3,4
        g_Wbig[idx] = (t < Kf) ? w[(t*96 + ki)*96 + ji] : 0.f;
    }
    if (idx < 288) {
        int f = idx / 96, ji = idx - f*96;
        g_bcat[idx] = ((f == 0) ? b2 : (f == 1) ? b3 : b4)[ji];
    }
}

// ---------------- tiled fp32 GEMM: BM=64, BN=96, BK=32, 256 thr, 4x6 micro ----------------
// which=0: concat = [T0|T1|T2|T3] @ Wbig + bcat   (K=384, out 288 wide)
// which=1: h = concat(scaled) @ fus_w + fus_b     (K=288, out 96 wide)
__global__ void k_gemm(int which, const float* __restrict__ fw, const float* __restrict__ fb) {
    __shared__ float As[64][36];
    __shared__ float Bs[32][96];
    const float* segs[4];
    const float* B; const float* bias; float* Cm;
    int K, lda, ldb, ldc;
    if (which == 0) {
        segs[0] = g_T0; segs[1] = g_T1; segs[2] = g_T2; segs[3] = g_T3;
        K = 384; lda = 96; B = g_Wbig; ldb = 288; bias = g_bcat; Cm = g_concat; ldc = 288;
    } else {
        segs[0] = g_concat; segs[1] = g_concat + 96; segs[2] = g_concat + 192; segs[3] = g_concat;
        K = 288; lda = 288; B = fw; ldb = 96; bias = fb; Cm = g_h; ldc = 96;
    }
    int tid = threadIdx.x;
    int tx = tid & 15, ty = tid >> 4;
    int row0 = blockIdx.y * 64, col0 = blockIdx.x * 96;
    float acc[4][6];
    #pragma unroll
    for (int r = 0; r < 4; r++)
        #pragma unroll
        for (int j = 0; j < 6; j++) acc[r][j] = 0.f;

    for (int kb = 0; kb < K; kb += 32) {
        const float* Ap = segs[kb/96] + (size_t)row0*lda + (kb % 96);
        {   // A tile: 64x32; thread loads 2 float4 from its row
            int r = tid >> 2;
            int cb = (tid & 3) * 4;
            #pragma unroll
            for (int i = 0; i < 2; i++) {
                float4 v = *(const float4*)(Ap + (size_t)r*lda + cb + i*16);
                *(float4*)&As[r][cb + i*16] = v;
            }
        }
        {   // B tile: 32x96; 768 float4 across 256 threads
            const float* Bp = B + (size_t)kb*ldb + col0;
            #pragma unroll
            for (int i = 0; i < 3; i++) {
                int f = tid + i*256;
                int r = f / 24, cq = f - r*24;
                float4 v = *(const float4*)(Bp + (size_t)r*ldb + cq*4);
                *(float4*)&Bs[r][cq*4] = v;
            }
        }
        __syncthreads();
        #pragma unroll
        for (int kk = 0; kk < 32; kk++) {
            float a0 = As[ty*4+0][kk], a1 = As[ty*4+1][kk];
            float a2 = As[ty*4+2][kk], a3 = As[ty*4+3][kk];
            float2 p0 = *(const float2*)&Bs[kk][tx*6];
            float2 p1 = *(const float2*)&Bs[kk][tx*6+2];
            float2 p2 = *(const float2*)&Bs[kk][tx*6+4];
            float b[6] = {p0.x, p0.y, p1.x, p1.y, p2.x, p2.y};
            #pragma unroll
            for (int j = 0; j < 6; j++) {
                acc[0][j] += a0*b[j]; acc[1][j] += a1*b[j];
                acc[2][j] += a2*b[j]; acc[3][j] += a3*b[j];
            }
        }
        __syncthreads();
    }
    #pragma unroll
    for (int r = 0; r < 4; r++) {
        int row = row0 + ty*4 + r;
        #pragma unroll
        for (int j = 0; j < 6; j++) {
            int colj = col0 + tx*6 + j;
            Cm[(size_t)row*ldc + colj] = acc[r][j] + bias[colj];
        }
    }
}

// ---------------- attention softmax + in-place scale (one warp per row) ----------------
__global__ void k_attn(const float* __restrict__ aw, const float* __restrict__ ab) {
    int gt = blockIdx.x*256 + threadIdx.x;
    int n = gt >> 5, lane = gt & 31;
    if (n >= NN) return;
    float* rowp = g_concat + (size_t)n * 288;
    float v[9];
    #pragma unroll
    for (int i = 0; i < 9; i++) v[i] = rowp[lane + i*32];
    float l0 = 0.f, l1 = 0.f, l2 = 0.f;
    #pragma unroll
    for (int i = 0; i < 9; i++) {
        int k = lane + i*32;
        float a = v[i];
        l0 += a * aw[k*3 + 0];
        l1 += a * aw[k*3 + 1];
        l2 += a * aw[k*3 + 2];
    }
    #pragma unroll
    for (int o = 16; o > 0; o >>= 1) {
        l0 += __shfl_xor_sync(0xffffffffu, l0, o);
        l1 += __shfl_xor_sync(0xffffffffu, l1, o);
        l2 += __shfl_xor_sync(0xffffffffu, l2, o);
    }
    l0 += ab[0]; l1 += ab[1]; l2 += ab[2];
    float m  = fmaxf(l0, fmaxf(l1, l2));
    float e0 = expf(l0 - m), e1 = expf(l1 - m), e2 = expf(l2 - m);
    float inv = 1.f / (e0 + e1 + e2);
    float s0 = e0*inv, s1 = e1*inv, s2 = e2*inv;
    #pragma unroll
    for (int i = 0; i < 9; i++) {
        int k = lane + i*32;
        int seg = k / 96;
        float sc = (seg == 0) ? s0 : (seg == 1) ? s1 : s2;
        rowp[k] = v[i] * sc;
    }
}

// ---------------- batchnorm stats / finalize / apply+relu ----------------
__global__ void k_bnstat() {
    int c = threadIdx.x, yy = threadIdx.y;   // block (96,4), grid 128
    float s = 0.f, s2 = 0.f;
    for (int n = blockIdx.x*4 + yy; n < NN; n += 512) {
        float v = g_h[(size_t)n*96 + c];
        s += v; s2 += v*v;
    }
    __shared__ float sh[4][96], sh2[4][96];
    sh[yy][c] = s; sh2[yy][c] = s2;
    __syncthreads();
    if (yy == 0) {
        double ts  = (double)sh[0][c]  + sh[1][c]  + sh[2][c]  + sh[3][c];
        double ts2 = (double)sh2[0][c] + sh2[1][c] + sh2[2][c] + sh2[3][c];
        atomicAdd(&g_bnsum[c],      ts);
        atomicAdd(&g_bnsum[96 + c], ts2);
    }
}

__global__ void k_bnfin(const float* __restrict__ gam, const float* __restrict__ bet) {
    int c = threadIdx.x;
    double mean = g_bnsum[c] / (double)NN;
    double var  = g_bnsum[96 + c] / (double)NN - mean*mean;
    float a = (float)((double)gam[c] / sqrt(var + 1e-5));
    g_bnab[c] = a;
    g_bnab[96 + c] = bet[c] - (float)mean * a;
}

__global__ void k_out(float* __restrict__ out) {
    int i = blockIdx.x*256 + threadIdx.x;
    if (i < NN*96) {
        int c = i % 96;
        float v = g_h[i] * g_bnab[c] + g_bnab[96 + c];
        out[i] = fmaxf(v, 0.f);
    }
}

// ---------------- launch ----------------
extern "C" void kernel_launch(void* const* d_in, const int* in_sizes, int n_in,
                              void* d_out, int out_size) {
    const float* x  = (const float*)d_in[0];
    const void*  ei = d_in[1];
    const float* w2 = (const float*)d_in[2];
    const float* b2 = (const float*)d_in[3];
    const float* w3 = (const float*)d_in[4];
    const float* b3 = (const float*)d_in[5];
    const float* w4 = (const float*)d_in[6];
    const float* b4 = (const float*)d_in[7];
    const float* aw = (const float*)d_in[8];
    const float* ab = (const float*)d_in[9];
    const float* fw = (const float*)d_in[10];
    const float* fb = (const float*)d_in[11];
    const float* gam = (const float*)d_in[12];
    const float* bet = (const float*)d_in[13];
    float* out = (float*)d_out;

    k_detect<<<1, 256>>>(ei);
    k_decode<<<(2*EE + 255)/256, 256>>>(ei);
    k_prep<<<(NC + 255)/256, 256>>>(x);
    k_zero_misc<<<(NN + 255)/256, 256>>>();
    k_deg<<<(EE + 255)/256, 256>>>();
    k_dis<<<(NN + 255)/256, 256>>>();
    k_wn<<<(EE + 255)/256, 256>>>();

    k_prop<<<(EE*24 + 255)/256, 256>>>(0, 1.0f);   // T1 = prop(T0)
    k_negT3<<<(NC + 255)/256, 256>>>();            // T3 = -T1
    k_prop<<<(EE*24 + 255)/256, 256>>>(1, 2.0f);   // T2 = 2*prop(T1) - T0
    k_prop<<<(EE*24 + 255)/256, 256>>>(2, 2.0f);   // T3 = 2*prop(T2) - T1

    k_buildW<<<(384*288 + 255)/256, 256>>>(w2, b2, w3, b3, w4, b4);
    dim3 g1(3, NPAD/64);
    k_gemm<<<g1, 256>>>(0, fw, fb);                // concat
    k_attn<<<(NN*32 + 255)/256, 256>>>(aw, ab);    // softmax + scale in place
    dim3 g2(1, NPAD/64);
    k_gemm<<<g2, 256>>>(1, fw, fb);                // fused projection -> h

    dim3 bs(96, 4);
    k_bnstat<<<128, bs>>>();
    k_bnfin<<<1, 96>>>(gam, bet);
    k_out<<<(NN*96 + 255)/256, 256>>>(out);
}

// round 2
// speedup vs baseline: 1.8505x; 1.8505x over previous
#include <cuda_runtime.h>
#include <math.h>

#define NN   50000
#define NPAD 50048
#define CCH  96
#define EE   800000
#define NC   (NPAD*CCH)
#define NB   49          // scan blocks: 49*1024 >= 50000

// ---------------- device scratch ----------------
__device__ float  g_T0[NC];
__device__ float  g_T1[NC];
__device__ float  g_T2[NC];
__device__ float  g_T3[NC];
__device__ float  g_concat[NPAD*288];
__device__ float  g_h[NC];
__device__ float  g_deg[NN];
__device__ float  g_dis[NN];
__device__ int    g_eidx[2*EE];
__device__ int    g_is64;
__device__ int    g_cnt[NN];
__device__ int    g_rowptr[NN+1];
__device__ int    g_cursor[NN];
__device__ int    g_bsum[NB];
__device__ int    g_boff[NB];
__device__ int    g_csrc[EE];
__device__ float  g_cw[EE];
__device__ float  g_Wbig[384*288];
__device__ float  g_bcat[288];
__device__ double g_bnsum[192];
__device__ float  g_bnab[192];

// ---------------- f32x2 helpers (sm_103a packed fp32) ----------------
__device__ __forceinline__ void ffma2(unsigned long long& d, unsigned long long a, unsigned long long b) {
    asm("fma.rn.f32x2 %0, %1, %2, %0;" : "+l"(d) : "l"(a), "l"(b));
}
__device__ __forceinline__ unsigned long long dupf(float v) {
    unsigned long long r; unsigned u = __float_as_uint(v);
    asm("mov.b64 %0, {%1,%1};" : "=l"(r) : "r"(u));
    return r;
}
__device__ __forceinline__ void unpack2(unsigned long long v, float& lo, float& hi) {
    unsigned a, b;
    asm("mov.b64 {%0,%1}, %2;" : "=r"(a), "=r"(b) : "l"(v));
    lo = __uint_as_float(a); hi = __uint_as_float(b);
}

// ---------------- edge dtype detect + decode ----------------
__global__ void k_detect(const void* ei) {
    __shared__ int any_nz;
    if (threadIdx.x == 0) any_nz = 0;
    __syncthreads();
    const int* p = (const int*)ei;
    int local = 0;
    for (int i = threadIdx.x; i < 4096; i += 256)
        if (p[2*i + 1] != 0) local = 1;
    if (local) atomicOr(&any_nz, 1);
    __syncthreads();
    if (threadIdx.x == 0) g_is64 = any_nz ? 0 : 1;
}

__global__ void k_decode(const void* ei) {
    int e = blockIdx.x*256 + threadIdx.x;
    if (e >= 2*EE) return;
    int v;
    if (g_is64) v = (int)((const long long*)ei)[e];
    else        v = ((const int*)ei)[e];
    g_eidx[e] = v;
}

// ---------------- prep: T0=x padded; pad rows of T1..T3 zeroed ----------------
__global__ void k_prep(const float* __restrict__ x) {
    int i = blockIdx.x*256 + threadIdx.x;
    if (i < NC) {
        float v = (i < NN*CCH) ? x[i] : 0.f;
        g_T0[i] = v;
        if (i >= NN*CCH) { g_T1[i] = 0.f; g_T2[i] = 0.f; g_T3[i] = 0.f; }
    }
}

__global__ void k_zero_misc() {
    int i = blockIdx.x*256 + threadIdx.x;
    if (i < NN)  { g_deg[i] = 0.f; g_cnt[i] = 0; }
    if (i < 192) g_bnsum[i] = 0.0;
}

// degree by row (for normalization) + count by col (for CSR)
__global__ void k_hist() {
    int e = blockIdx.x*256 + threadIdx.x;
    if (e < EE) {
        atomicAdd(&g_deg[g_eidx[e]], 1.0f);
        atomicAdd(&g_cnt[g_eidx[EE + e]], 1);
    }
}

__global__ void k_dis() {
    int i = blockIdx.x*256 + threadIdx.x;
    if (i < NN) {
        float d = g_deg[i];
        g_dis[i] = (d > 0.f) ? rsqrtf(d) : 0.f;
    }
}

// ---------------- prefix scan over g_cnt -> g_rowptr ----------------
__global__ void k_scan1() {
    __shared__ int s[1024];
    int tid = threadIdx.x;
    int i = blockIdx.x*1024 + tid;
    int v = (i < NN) ? g_cnt[i] : 0;
    s[tid] = v;
    __syncthreads();
    for (int off = 1; off < 1024; off <<= 1) {
        int t = (tid >= off) ? s[tid - off] : 0;
        __syncthreads();
        s[tid] += t;
        __syncthreads();
    }
    if (i < NN) g_rowptr[i] = s[tid] - v;   // exclusive
    if (tid == 1023) g_bsum[blockIdx.x] = s[tid];
}

__global__ void k_scan2() {
    if (threadIdx.x == 0) {
        int acc = 0;
        for (int b = 0; b < NB; b++) { g_boff[b] = acc; acc += g_bsum[b]; }
        g_rowptr[NN] = EE;
    }
}

__global__ void k_scan3() {
    int i = blockIdx.x*256 + threadIdx.x;
    if (i < NN) {
        int v = g_rowptr[i] + g_boff[i >> 10];
        g_rowptr[i] = v;
        g_cursor[i] = v;
    }
}

__global__ void k_scatter() {
    int e = blockIdx.x*256 + threadIdx.x;
    if (e >= EE) return;
    int r = g_eidx[e], c = g_eidx[EE + e];
    int pos = atomicAdd(&g_cursor[c], 1);
    g_csrc[pos] = r;
    g_cw[pos] = -g_dis[r] * g_dis[c];
}

// ---------------- CSR propagation: one warp per dst node, 3 ch/lane ----------------
// which=0: T1 = prop(T0)            (coef=1, sub=none)
// which=1: T2 = 2*prop(T1) - T0
// which=2: T3 = 2*prop(T2) - T1
__global__ void k_prop_csr(int which) {
    const float* src; const float* sub; float* dst; float coef;
    if (which == 0)      { src = g_T0; sub = 0;    dst = g_T1; coef = 1.f; }
    else if (which == 1) { src = g_T1; sub = g_T0; dst = g_T2; coef = 2.f; }
    else                 { src = g_T2; sub = g_T1; dst = g_T3; coef = 2.f; }
    int w = (blockIdx.x*blockDim.x + threadIdx.x) >> 5;
    int lane = threadIdx.x & 31;
    if (w >= NN) return;
    int beg = g_rowptr[w], end = g_rowptr[w + 1];
    float a0 = 0.f, a1 = 0.f, a2 = 0.f;
    int i = beg;
    for (; i + 1 < end; i += 2) {
        int   r0 = g_csrc[i],   r1 = g_csrc[i+1];
        float w0 = g_cw[i],     w1 = g_cw[i+1];
        const float* s0 = src + (size_t)r0*CCH;
        const float* s1 = src + (size_t)r1*CCH;
        float x0 = s0[lane], x1 = s0[lane+32], x2 = s0[lane+64];
        float y0 = s1[lane], y1 = s1[lane+32], y2 = s1[lane+64];
        a0 += w0*x0 + w1*y0;
        a1 += w0*x1 + w1*y1;
        a2 += w0*x2 + w1*y2;
    }
    if (i < end) {
        int r0 = g_csrc[i]; float w0 = g_cw[i];
        const float* s0 = src + (size_t)r0*CCH;
        a0 += w0*s0[lane]; a1 += w0*s0[lane+32]; a2 += w0*s0[lane+64];
    }
    float* dp = dst + (size_t)w*CCH;
    if (sub) {
        const float* sp = sub + (size_t)w*CCH;
        dp[lane]    = coef*a0 - sp[lane];
        dp[lane+32] = coef*a1 - sp[lane+32];
        dp[lane+64] = coef*a2 - sp[lane+64];
    } else {
        dp[lane] = a0; dp[lane+32] = a1; dp[lane+64] = a2;
    }
}

// ---------------- build block weight [384,288] + bias concat ----------------
__global__ void k_buildW(const float* __restrict__ w2, const float* __restrict__ b2,
                         const float* __restrict__ w3, const float* __restrict__ b3,
                         const float* __restrict__ w4, const float* __restrict__ b4) {
    int idx = blockIdx.x*256 + threadIdx.x;
    if (idx < 384*288) {
        int k = idx / 288, j = idx - k*288;
        int t = k / 96,  ki = k - t*96;
        int f = j / 96,  ji = j - f*96;
        const float* w = (f == 0) ? w2 : (f == 1) ? w3 : w4;
        int Kf = f + 2;
        g_Wbig[idx] = (t < Kf) ? w[(t*96 + ki)*96 + ji] : 0.f;
    }
    if (idx < 288) {
        int f = idx / 96, ji = idx - f*96;
        g_bcat[idx] = ((f == 0) ? b2 : (f == 1) ? b3 : b4)[ji];
    }
}

// ---------------- GEMM: BM=128 BN=96 BK=16, 256 thr, 8x6 micro via fma.f32x2 ----------------
// which=0: concat = [T0|T1|T2|T3] @ Wbig + bcat; block col f uses K=96*(f+2)
// which=1: h = concat @ fus_w + fus_b (K=288)
__global__ void __launch_bounds__(256) k_gemm(int which, const float* __restrict__ fw,
                                              const float* __restrict__ fb) {
    __shared__ float AsT[16][138];
    __shared__ float Bs[16][96];
    int tid = threadIdx.x;
    int tx = tid & 15, ty = tid >> 4;
    int row0 = blockIdx.y * 128;
    int col0, K, ldb, ldc;
    const float* Bg; const float* bias; float* Cm;
    if (which == 0) {
        col0 = blockIdx.x*96; K = 96*((int)blockIdx.x + 2);
        Bg = g_Wbig; ldb = 288; bias = g_bcat; Cm = g_concat; ldc = 288;
    } else {
        col0 = 0; K = 288;
        Bg = fw; ldb = 96; bias = fb; Cm = g_h; ldc = 96;
    }
    unsigned long long acc[4][6];
    #pragma unroll
    for (int r = 0; r < 4; r++)
        #pragma unroll
        for (int j = 0; j < 6; j++) acc[r][j] = 0ull;

    int arow = tid >> 1;
    int ak = (tid & 1) * 8;

    for (int kb = 0; kb < K; kb += 16) {
        // ---- A tile load: 128x16, each thread 2 float4, store k-major ----
        const float* Ap; int lda;
        if (which == 0) {
            int sg = kb / 96;
            const float* base = (sg == 0) ? g_T0 : (sg == 1) ? g_T1 : (sg == 2) ? g_T2 : g_T3;
            Ap = base + (size_t)row0*96 + (kb - sg*96);
            lda = 96;
        } else {
            Ap = g_concat + (size_t)row0*288 + kb;
            lda = 288;
        }
        float4 v0 = *(const float4*)(Ap + (size_t)arow*lda + ak);
        float4 v1 = *(const float4*)(Ap + (size_t)arow*lda + ak + 4);
        AsT[ak+0][arow] = v0.x; AsT[ak+1][arow] = v0.y;
        AsT[ak+2][arow] = v0.z; AsT[ak+3][arow] = v0.w;
        AsT[ak+4][arow] = v1.x; AsT[ak+5][arow] = v1.y;
        AsT[ak+6][arow] = v1.z; AsT[ak+7][arow] = v1.w;
        // ---- B tile load: 16x96 = 384 float4 ----
        const float* Bp = Bg + (size_t)kb*ldb + col0;
        #pragma unroll
        for (int f = 0; f < 2; f++) {
            int id = tid + f*256;
            if (id < 384) {
                int r = id / 24, c = id - r*24;
                float4 v = *(const float4*)(Bp + (size_t)r*ldb + c*4);
                *(float4*)&Bs[r][c*4] = v;
            }
        }
        __syncthreads();
        #pragma unroll
        for (int kk = 0; kk < 16; kk++) {
            unsigned long long a0 = *(const unsigned long long*)&AsT[kk][ty*8 + 0];
            unsigned long long a1 = *(const unsigned long long*)&AsT[kk][ty*8 + 2];
            unsigned long long a2 = *(const unsigned long long*)&AsT[kk][ty*8 + 4];
            unsigned long long a3 = *(const unsigned long long*)&AsT[kk][ty*8 + 6];
            float2 b01 = *(const float2*)&Bs[kk][tx*6];
            float2 b23 = *(const float2*)&Bs[kk][tx*6 + 2];
            float2 b45 = *(const float2*)&Bs[kk][tx*6 + 4];
            unsigned long long bb[6];
            bb[0] = dupf(b01.x); bb[1] = dupf(b01.y);
            bb[2] = dupf(b23.x); bb[3] = dupf(b23.y);
            bb[4] = dupf(b45.x); bb[5] = dupf(b45.y);
            #pragma unroll
            for (int j = 0; j < 6; j++) {
                ffma2(acc[0][j], a0, bb[j]);
                ffma2(acc[1][j], a1, bb[j]);
                ffma2(acc[2][j], a2, bb[j]);
                ffma2(acc[3][j], a3, bb[j]);
            }
        }
        __syncthreads();
    }
    // ---- epilogue ----
    #pragma unroll
    for (int r = 0; r < 4; r++) {
        int rowe = row0 + ty*8 + 2*r;
        #pragma unroll
        for (int j = 0; j < 6; j++) {
            int col = col0 + tx*6 + j;
            float lo, hi;
            unpack2(acc[r][j], lo, hi);
            float b = bias[col];
            Cm[(size_t)rowe*ldc + col]       = lo + b;
            Cm[(size_t)(rowe+1)*ldc + col]   = hi + b;
        }
    }
}

// ---------------- attention softmax + in-place scale (1 warp / row) ----------------
__global__ void k_attn(const float* __restrict__ aw, const float* __restrict__ ab) {
    int gt = blockIdx.x*256 + threadIdx.x;
    int n = gt >> 5, lane = gt & 31;
    if (n >= NN) return;
    float* rowp = g_concat + (size_t)n * 288;
    float v[9];
    #pragma unroll
    for (int i = 0; i < 9; i++) v[i] = rowp[lane + i*32];
    float l0 = 0.f, l1 = 0.f, l2 = 0.f;
    #pragma unroll
    for (int i = 0; i < 9; i++) {
        int k = lane + i*32;
        float a = v[i];
        l0 += a * aw[k*3 + 0];
        l1 += a * aw[k*3 + 1];
        l2 += a * aw[k*3 + 2];
    }
    #pragma unroll
    for (int o = 16; o > 0; o >>= 1) {
        l0 += __shfl_xor_sync(0xffffffffu, l0, o);
        l1 += __shfl_xor_sync(0xffffffffu, l1, o);
        l2 += __shfl_xor_sync(0xffffffffu, l2, o);
    }
    l0 += ab[0]; l1 += ab[1]; l2 += ab[2];
    float m  = fmaxf(l0, fmaxf(l1, l2));
    float e0 = expf(l0 - m), e1 = expf(l1 - m), e2 = expf(l2 - m);
    float inv = 1.f / (e0 + e1 + e2);
    float s0 = e0*inv, s1 = e1*inv, s2 = e2*inv;
    #pragma unroll
    for (int i = 0; i < 9; i++) {
        int k = lane + i*32;
        int seg = k / 96;
        float sc = (seg == 0) ? s0 : (seg == 1) ? s1 : s2;
        rowp[k] = v[i] * sc;
    }
}

// ---------------- batchnorm ----------------
__global__ void k_bnstat() {
    int c = threadIdx.x, yy = threadIdx.y;
    float s = 0.f, s2 = 0.f;
    for (int n = blockIdx.x*4 + yy; n < NN; n += 512) {
        float v = g_h[(size_t)n*96 + c];
        s += v; s2 += v*v;
    }
    __shared__ float sh[4][96], sh2[4][96];
    sh[yy][c] = s; sh2[yy][c] = s2;
    __syncthreads();
    if (yy == 0) {
        double ts  = (double)sh[0][c]  + sh[1][c]  + sh[2][c]  + sh[3][c];
        double ts2 = (double)sh2[0][c] + sh2[1][c] + sh2[2][c] + sh2[3][c];
        atomicAdd(&g_bnsum[c],      ts);
        atomicAdd(&g_bnsum[96 + c], ts2);
    }
}

__global__ void k_bnfin(const float* __restrict__ gam, const float* __restrict__ bet) {
    int c = threadIdx.x;
    double mean = g_bnsum[c] / (double)NN;
    double var  = g_bnsum[96 + c] / (double)NN - mean*mean;
    float a = (float)((double)gam[c] / sqrt(var + 1e-5));
    g_bnab[c] = a;
    g_bnab[96 + c] = bet[c] - (float)mean * a;
}

__global__ void k_out(float* __restrict__ out) {
    int i = blockIdx.x*256 + threadIdx.x;
    if (i < NN*96) {
        int c = i % 96;
        float v = g_h[i] * g_bnab[c] + g_bnab[96 + c];
        out[i] = fmaxf(v, 0.f);
    }
}

// ---------------- launch ----------------
extern "C" void kernel_launch(void* const* d_in, const int* in_sizes, int n_in,
                              void* d_out, int out_size) {
    const float* x  = (const float*)d_in[0];
    const void*  ei = d_in[1];
    const float* w2 = (const float*)d_in[2];
    const float* b2 = (const float*)d_in[3];
    const float* w3 = (const float*)d_in[4];
    const float* b3 = (const float*)d_in[5];
    const float* w4 = (const float*)d_in[6];
    const float* b4 = (const float*)d_in[7];
    const float* aw = (const float*)d_in[8];
    const float* ab = (const float*)d_in[9];
    const float* fw = (const float*)d_in[10];
    const float* fb = (const float*)d_in[11];
    const float* gam = (const float*)d_in[12];
    const float* bet = (const float*)d_in[13];
    float* out = (float*)d_out;

    k_detect<<<1, 256>>>(ei);
    k_decode<<<(2*EE + 255)/256, 256>>>(ei);
    k_prep<<<(NC + 255)/256, 256>>>(x);
    k_zero_misc<<<(NN + 255)/256, 256>>>();
    k_hist<<<(EE + 255)/256, 256>>>();
    k_dis<<<(NN + 255)/256, 256>>>();
    k_scan1<<<NB, 1024>>>();
    k_scan2<<<1, 32>>>();
    k_scan3<<<(NN + 255)/256, 256>>>();
    k_scatter<<<(EE + 255)/256, 256>>>();

    k_prop_csr<<<(NN*32 + 255)/256, 256>>>(0);   // T1
    k_prop_csr<<<(NN*32 + 255)/256, 256>>>(1);   // T2
    k_prop_csr<<<(NN*32 + 255)/256, 256>>>(2);   // T3

    k_buildW<<<(384*288 + 255)/256, 256>>>(w2, b2, w3, b3, w4, b4);
    dim3 g1(3, NPAD/128);
    k_gemm<<<g1, 256>>>(0, fw, fb);
    k_attn<<<(NN*32 + 255)/256, 256>>>(aw, ab);
    dim3 g2(1, NPAD/128);
    k_gemm<<<g2, 256>>>(1, fw, fb);

    dim3 bs(96, 4);
    k_bnstat<<<128, bs>>>();
    k_bnfin<<<1, 96>>>(gam, bet);
    k_out<<<(NN*96 + 255)/256, 256>>>(out);
}

// round 5
// speedup vs baseline: 2.1007x; 1.1352x over previous
#include <cuda_runtime.h>
#include <math.h>

#define NN   50000
#define NPAD 50048
#define CCH  96
#define EE   800000
#define NC   (NPAD*CCH)
#define NB   49          // scan blocks: 49*1024 >= 50000

// ---------------- device scratch ----------------
__device__ float  g_T1[NC];
__device__ float  g_T2[NC];
__device__ float  g_T3[NC];
__device__ float  g_concat[NPAD*288];
__device__ float  g_h[NC];
__device__ float  g_deg[NN];
__device__ float  g_dis[NN];
__device__ int    g_eidx[2*EE];
__device__ int    g_is64;
__device__ int    g_cnt[NN];
__device__ int    g_rowptr[NN+1];
__device__ int    g_cursor[NN];
__device__ int    g_bsum[NB];
__device__ int    g_csrc[EE];
__device__ float  g_cw[EE];
__device__ float  g_Wbig[384*288];
__device__ float  g_bcat[288];
__device__ float  g_logits[NPAD*4];
__device__ float  g_scalew[NPAD*4];
__device__ double g_bnsum[192];
__device__ float  g_bnab[192];

// ---------------- f32x2 helpers (sm_103a packed fp32) ----------------
__device__ __forceinline__ void ffma2(unsigned long long& d, unsigned long long a, unsigned long long b) {
    asm("fma.rn.f32x2 %0, %1, %2, %0;" : "+l"(d) : "l"(a), "l"(b));
}
__device__ __forceinline__ unsigned long long dupf(float v) {
    unsigned long long r; unsigned u = __float_as_uint(v);
    asm("mov.b64 %0, {%1,%1};" : "=l"(r) : "r"(u));
    return r;
}
__device__ __forceinline__ void unpack2(unsigned long long v, float& lo, float& hi) {
    unsigned a, b;
    asm("mov.b64 {%0,%1}, %2;" : "=r"(a), "=r"(b) : "l"(v));
    lo = __uint_as_float(a); hi = __uint_as_float(b);
}

// ---------------- init: zero counters + edge dtype detect ----------------
__global__ void k_init(const void* ei) {
    int i = blockIdx.x*256 + threadIdx.x;
    if (i < NN)  { g_deg[i] = 0.f; g_cnt[i] = 0; }
    if (i < 192) g_bnsum[i] = 0.0;
    if (i < NPAD*4) { g_logits[i] = 0.f; g_scalew[i] = 0.f; }
    if (blockIdx.x == 0) {
        __shared__ int any_nz;
        if (threadIdx.x == 0) any_nz = 0;
        __syncthreads();
        const int* p = (const int*)ei;
        int local = 0;
        for (int j = threadIdx.x; j < 4096; j += 256)
            if (p[2*j + 1] != 0) local = 1;
        if (local) atomicOr(&any_nz, 1);
        __syncthreads();
        if (threadIdx.x == 0) g_is64 = any_nz ? 0 : 1;
    }
}

// ---------------- decode + degree/count histogram ----------------
__global__ void k_decode_hist(const void* ei) {
    int e = blockIdx.x*256 + threadIdx.x;
    if (e >= 2*EE) return;
    int v;
    if (g_is64) v = (int)((const long long*)ei)[e];
    else        v = ((const int*)ei)[e];
    g_eidx[e] = v;
    if (e < EE) atomicAdd(&g_deg[v], 1.0f);
    else        atomicAdd(&g_cnt[v], 1);
}

// ---------------- prefix scan ----------------
__global__ void k_scan1() {
    __shared__ int s[1024];
    int tid = threadIdx.x;
    int i = blockIdx.x*1024 + tid;
    int v = (i < NN) ? g_cnt[i] : 0;
    s[tid] = v;
    __syncthreads();
    for (int off = 1; off < 1024; off <<= 1) {
        int t = (tid >= off) ? s[tid - off] : 0;
        __syncthreads();
        s[tid] += t;
        __syncthreads();
    }
    if (i < NN) g_rowptr[i] = s[tid] - v;   // exclusive within block
    if (tid == 1023) g_bsum[blockIdx.x] = s[tid];
}

// merged: block-offset add + cursor + dis
__global__ void k_scan23() {
    int i = blockIdx.x*256 + threadIdx.x;
    if (i == 0) g_rowptr[NN] = EE;
    if (i < NN) {
        int b = i >> 10;
        int off = 0;
        for (int k = 0; k < b; k++) off += g_bsum[k];
        int v = g_rowptr[i] + off;
        g_rowptr[i] = v;
        g_cursor[i] = v;
        float d = g_deg[i];
        g_dis[i] = (d > 0.f) ? rsqrtf(d) : 0.f;
    }
}

__global__ void k_scatter() {
    int e = blockIdx.x*256 + threadIdx.x;
    if (e >= EE) return;
    int r = g_eidx[e], c = g_eidx[EE + e];
    int pos = atomicAdd(&g_cursor[c], 1);
    g_csrc[pos] = r;
    g_cw[pos] = -g_dis[r] * g_dis[c];
}

// ---------------- CSR propagation: one warp per dst, 3 ch/lane, 4-edge unroll ----------------
// which=0: T1 = prop(x)
// which=1: T2 = 2*prop(T1) - x
// which=2: T3 = 2*prop(T2) - T1
__global__ void k_prop_csr(const float* __restrict__ x, int which) {
    const float* src; const float* sub; float* dst; float coef;
    if (which == 0)      { src = x;    sub = 0;    dst = g_T1; coef = 1.f; }
    else if (which == 1) { src = g_T1; sub = x;    dst = g_T2; coef = 2.f; }
    else                 { src = g_T2; sub = g_T1; dst = g_T3; coef = 2.f; }
    int w = (blockIdx.x*blockDim.x + threadIdx.x) >> 5;
    int lane = threadIdx.x & 31;
    if (w >= NN) return;
    int beg = g_rowptr[w], end = g_rowptr[w + 1];
    float a0 = 0.f, a1 = 0.f, a2 = 0.f;
    int i = beg;
    for (; i + 4 <= end; i += 4) {
        int   r0 = g_csrc[i],   r1 = g_csrc[i+1], r2 = g_csrc[i+2], r3 = g_csrc[i+3];
        float w0 = g_cw[i],     w1 = g_cw[i+1],   w2 = g_cw[i+2],   w3 = g_cw[i+3];
        const float* s0 = src + (size_t)r0*CCH;
        const float* s1 = src + (size_t)r1*CCH;
        const float* s2 = src + (size_t)r2*CCH;
        const float* s3 = src + (size_t)r3*CCH;
        float p00 = s0[lane], p01 = s0[lane+32], p02 = s0[lane+64];
        float p10 = s1[lane], p11 = s1[lane+32], p12 = s1[lane+64];
        float p20 = s2[lane], p21 = s2[lane+32], p22 = s2[lane+64];
        float p30 = s3[lane], p31 = s3[lane+32], p32 = s3[lane+64];
        a0 += w0*p00 + w1*p10 + w2*p20 + w3*p30;
        a1 += w0*p01 + w1*p11 + w2*p21 + w3*p31;
        a2 += w0*p02 + w1*p12 + w2*p22 + w3*p32;
    }
    for (; i < end; i++) {
        int r0 = g_csrc[i]; float w0 = g_cw[i];
        const float* s0 = src + (size_t)r0*CCH;
        a0 += w0*s0[lane]; a1 += w0*s0[lane+32]; a2 += w0*s0[lane+64];
    }
    float* dp = dst + (size_t)w*CCH;
    if (sub) {
        const float* sp = sub + (size_t)w*CCH;
        dp[lane]    = coef*a0 - sp[lane];
        dp[lane+32] = coef*a1 - sp[lane+32];
        dp[lane+64] = coef*a2 - sp[lane+64];
    } else {
        dp[lane] = a0; dp[lane+32] = a1; dp[lane+64] = a2;
    }
}

// ---------------- build block weight [384,288] + bias concat ----------------
__global__ void k_buildW(const float* __restrict__ w2, const float* __restrict__ b2,
                         const float* __restrict__ w3, const float* __restrict__ b3,
                         const float* __restrict__ w4, const float* __restrict__ b4) {
    int idx = blockIdx.x*256 + threadIdx.x;
    if (idx < 384*288) {
        int k = idx / 288, j = idx - k*288;
        int t = k / 96,  ki = k - t*96;
        int f = j / 96,  ji = j - f*96;
        const float* w = (f == 0) ? w2 : (f == 1) ? w3 : w4;
        int Kf = f + 2;
        g_Wbig[idx] = (t < Kf) ? w[(t*96 + ki)*96 + ji] : 0.f;
    }
    if (idx < 288) {
        int f = idx / 96, ji = idx - f*96;
        g_bcat[idx] = ((f == 0) ? b2 : (f == 1) ? b3 : b4)[ji];
    }
}

// ---------------- GEMM1: concat = [x|T1|T2|T3] @ Wbig + bcat, + attn-logit epilogue ----------------
// grid (3, NPAD/128); block col f uses K=96*(f+2)
__global__ void __launch_bounds__(256) k_gemm1(const float* __restrict__ x,
                                               const float* __restrict__ aw) {
    __shared__ float AsT[16][138];
    __shared__ float Bs[16][96];
    int tid = threadIdx.x;
    int tx = tid & 15, ty = tid >> 4;
    int f = blockIdx.x;
    int row0 = blockIdx.y * 128;
    int col0 = f*96;
    int K = 96*(f + 2);
    unsigned long long acc[4][6];
    #pragma unroll
    for (int r = 0; r < 4; r++)
        #pragma unroll
        for (int j = 0; j < 6; j++) acc[r][j] = 0ull;

    int arow = tid >> 1;
    int ak = (tid & 1) * 8;
    int grow = row0 + arow;

    for (int kb = 0; kb < K; kb += 16) {
        int sg = kb / 96;
        const float* base = (sg == 0) ? x : (sg == 1) ? g_T1 : (sg == 2) ? g_T2 : g_T3;
        int aoff = kb - sg*96;
        float4 v0 = make_float4(0.f,0.f,0.f,0.f), v1 = v0;
        if (grow < NN) {
            v0 = *(const float4*)(base + (size_t)grow*96 + aoff + ak);
            v1 = *(const float4*)(base + (size_t)grow*96 + aoff + ak + 4);
        }
        AsT[ak+0][arow] = v0.x; AsT[ak+1][arow] = v0.y;
        AsT[ak+2][arow] = v0.z; AsT[ak+3][arow] = v0.w;
        AsT[ak+4][arow] = v1.x; AsT[ak+5][arow] = v1.y;
        AsT[ak+6][arow] = v1.z; AsT[ak+7][arow] = v1.w;
        const float* Bp = g_Wbig + (size_t)kb*288 + col0;
        #pragma unroll
        for (int f2 = 0; f2 < 2; f2++) {
            int id = tid + f2*256;
            if (id < 384) {
                int r = id / 24, c = id - r*24;
                float4 v = *(const float4*)(Bp + (size_t)r*288 + c*4);
                *(float4*)&Bs[r][c*4] = v;
            }
        }
        __syncthreads();
        #pragma unroll
        for (int kk = 0; kk < 16; kk++) {
            unsigned long long a0 = *(const unsigned long long*)&AsT[kk][ty*8 + 0];
            unsigned long long a1 = *(const unsigned long long*)&AsT[kk][ty*8 + 2];
            unsigned long long a2 = *(const unsigned long long*)&AsT[kk][ty*8 + 4];
            unsigned long long a3 = *(const unsigned long long*)&AsT[kk][ty*8 + 6];
            float2 b01 = *(const float2*)&Bs[kk][tx*6];
            float2 b23 = *(const float2*)&Bs[kk][tx*6 + 2];
            float2 b45 = *(const float2*)&Bs[kk][tx*6 + 4];
            unsigned long long bb[6];
            bb[0] = dupf(b01.x); bb[1] = dupf(b01.y);
            bb[2] = dupf(b23.x); bb[3] = dupf(b23.y);
            bb[4] = dupf(b45.x); bb[5] = dupf(b45.y);
            #pragma unroll
            for (int j = 0; j < 6; j++) {
                ffma2(acc[0][j], a0, bb[j]);
                ffma2(acc[1][j], a1, bb[j]);
                ffma2(acc[2][j], a2, bb[j]);
                ffma2(acc[3][j], a3, bb[j]);
            }
        }
        __syncthreads();
    }
    // epilogue: write concat + accumulate attention logits (3 per row)
    float awr[3][6];
    #pragma unroll
    for (int j = 0; j < 6; j++) {
        int col = col0 + tx*6 + j;
        awr[0][j] = aw[col*3 + 0];
        awr[1][j] = aw[col*3 + 1];
        awr[2][j] = aw[col*3 + 2];
    }
    #pragma unroll
    for (int r = 0; r < 4; r++) {
        int rowe = row0 + ty*8 + 2*r;
        float lo[6], hi[6];
        #pragma unroll
        for (int j = 0; j < 6; j++) {
            float l_, h_;
            unpack2(acc[r][j], l_, h_);
            int col = col0 + tx*6 + j;
            float b = g_bcat[col];
            lo[j] = l_ + b; hi[j] = h_ + b;
            g_concat[(size_t)rowe*288 + col]     = lo[j];
            g_concat[(size_t)(rowe+1)*288 + col] = hi[j];
        }
        float ll0=0.f, ll1=0.f, ll2=0.f, lh0=0.f, lh1=0.f, lh2=0.f;
        #pragma unroll
        for (int j = 0; j < 6; j++) {
            ll0 += lo[j]*awr[0][j]; ll1 += lo[j]*awr[1][j]; ll2 += lo[j]*awr[2][j];
            lh0 += hi[j]*awr[0][j]; lh1 += hi[j]*awr[1][j]; lh2 += hi[j]*awr[2][j];
        }
        #pragma unroll
        for (int o = 1; o < 16; o <<= 1) {
            ll0 += __shfl_xor_sync(0xffffffffu, ll0, o);
            ll1 += __shfl_xor_sync(0xffffffffu, ll1, o);
            ll2 += __shfl_xor_sync(0xffffffffu, ll2, o);
            lh0 += __shfl_xor_sync(0xffffffffu, lh0, o);
            lh1 += __shfl_xor_sync(0xffffffffu, lh1, o);
            lh2 += __shfl_xor_sync(0xffffffffu, lh2, o);
        }
        if (tx == 0) {
            if (rowe < NN) {
                atomicAdd(&g_logits[rowe*4 + 0], ll0);
                atomicAdd(&g_logits[rowe*4 + 1], ll1);
                atomicAdd(&g_logits[rowe*4 + 2], ll2);
            }
            if (rowe + 1 < NN) {
                atomicAdd(&g_logits[(rowe+1)*4 + 0], lh0);
                atomicAdd(&g_logits[(rowe+1)*4 + 1], lh1);
                atomicAdd(&g_logits[(rowe+1)*4 + 2], lh2);
            }
        }
    }
}

// ---------------- attention: softmax over the 3 accumulated logits ----------------
__global__ void k_attn(const float* __restrict__ ab) {
    int n = blockIdx.x*256 + threadIdx.x;
    if (n >= NN) return;
    float l0 = g_logits[n*4 + 0] + ab[0];
    float l1 = g_logits[n*4 + 1] + ab[1];
    float l2 = g_logits[n*4 + 2] + ab[2];
    float m  = fmaxf(l0, fmaxf(l1, l2));
    float e0 = expf(l0 - m), e1 = expf(l1 - m), e2 = expf(l2 - m);
    float inv = 1.f / (e0 + e1 + e2);
    g_scalew[n*4 + 0] = e0*inv;
    g_scalew[n*4 + 1] = e1*inv;
    g_scalew[n*4 + 2] = e2*inv;
}

// ---------------- GEMM2: h = (concat * scalew) @ fus_w + fb, + BN-stat epilogue ----------------
// grid (1, NPAD/128)
__global__ void __launch_bounds__(256) k_gemm2(const float* __restrict__ fw,
                                               const float* __restrict__ fb) {
    __shared__ float AsT[16][138];
    __shared__ float Bs[16][96];
    __shared__ float sh_s[96], sh_s2[96];
    int tid = threadIdx.x;
    if (tid < 96) { sh_s[tid] = 0.f; sh_s2[tid] = 0.f; }
    int tx = tid & 15, ty = tid >> 4;
    int row0 = blockIdx.y * 128;
    unsigned long long acc[4][6];
    #pragma unroll
    for (int r = 0; r < 4; r++)
        #pragma unroll
        for (int j = 0; j < 6; j++) acc[r][j] = 0ull;

    int arow = tid >> 1;
    int ak = (tid & 1) * 8;
    int grow = row0 + arow;

    for (int kb = 0; kb < 288; kb += 16) {
        int seg = kb / 96;
        float4 v0 = make_float4(0.f,0.f,0.f,0.f), v1 = v0;
        if (grow < NN) {
            float sc = g_scalew[grow*4 + seg];
            v0 = *(const float4*)(g_concat + (size_t)grow*288 + kb + ak);
            v1 = *(const float4*)(g_concat + (size_t)grow*288 + kb + ak + 4);
            v0.x *= sc; v0.y *= sc; v0.z *= sc; v0.w *= sc;
            v1.x *= sc; v1.y *= sc; v1.z *= sc; v1.w *= sc;
        }
        AsT[ak+0][arow] = v0.x; AsT[ak+1][arow] = v0.y;
        AsT[ak+2][arow] = v0.z; AsT[ak+3][arow] = v0.w;
        AsT[ak+4][arow] = v1.x; AsT[ak+5][arow] = v1.y;
        AsT[ak+6][arow] = v1.z; AsT[ak+7][arow] = v1.w;
        const float* Bp = fw + (size_t)kb*96;
        #pragma unroll
        for (int f2 = 0; f2 < 2; f2++) {
            int id = tid + f2*256;
            if (id < 384) {
                int r = id / 24, c = id - r*24;
                float4 v = *(const float4*)(Bp + (size_t)r*96 + c*4);
                *(float4*)&Bs[r][c*4] = v;
            }
        }
        __syncthreads();
        #pragma unroll
        for (int kk = 0; kk < 16; kk++) {
            unsigned long long a0 = *(const unsigned long long*)&AsT[kk][ty*8 + 0];
            unsigned long long a1 = *(const unsigned long long*)&AsT[kk][ty*8 + 2];
            unsigned long long a2 = *(const unsigned long long*)&AsT[kk][ty*8 + 4];
            unsigned long long a3 = *(const unsigned long long*)&AsT[kk][ty*8 + 6];
            float2 b01 = *(const float2*)&Bs[kk][tx*6];
            float2 b23 = *(const float2*)&Bs[kk][tx*6 + 2];
            float2 b45 = *(const float2*)&Bs[kk][tx*6 + 4];
            unsigned long long bb[6];
            bb[0] = dupf(b01.x); bb[1] = dupf(b01.y);
            bb[2] = dupf(b23.x); bb[3] = dupf(b23.y);
            bb[4] = dupf(b45.x); bb[5] = dupf(b45.y);
            #pragma unroll
            for (int j = 0; j < 6; j++) {
                ffma2(acc[0][j], a0, bb[j]);
                ffma2(acc[1][j], a1, bb[j]);
                ffma2(acc[2][j], a2, bb[j]);
                ffma2(acc[3][j], a3, bb[j]);
            }
        }
        __syncthreads();
    }
    // epilogue: write h + BN partial sums
    float scol[6], s2col[6];
    #pragma unroll
    for (int j = 0; j < 6; j++) { scol[j] = 0.f; s2col[j] = 0.f; }
    #pragma unroll
    for (int r = 0; r < 4; r++) {
        int rowe = row0 + ty*8 + 2*r;
        #pragma unroll
        for (int j = 0; j < 6; j++) {
            float l_, h_;
            unpack2(acc[r][j], l_, h_);
            int col = tx*6 + j;
            float b = fb[col];
            l_ += b; h_ += b;
            if (rowe < NN) {
                g_h[(size_t)rowe*96 + col] = l_;
                scol[j] += l_; s2col[j] += l_*l_;
            }
            if (rowe + 1 < NN) {
                g_h[(size_t)(rowe+1)*96 + col] = h_;
                scol[j] += h_; s2col[j] += h_*h_;
            }
        }
    }
    #pragma unroll
    for (int j = 0; j < 6; j++) {
        atomicAdd(&sh_s[tx*6 + j],  scol[j]);
        atomicAdd(&sh_s2[tx*6 + j], s2col[j]);
    }
    __syncthreads();
    if (tid < 96) {
        atomicAdd(&g_bnsum[tid],      (double)sh_s[tid]);
        atomicAdd(&g_bnsum[96 + tid], (double)sh_s2[tid]);
    }
}

// ---------------- batchnorm finalize + output ----------------
__global__ void k_bnfin(const float* __restrict__ gam, const float* __restrict__ bet) {
    int c = threadIdx.x;
    double mean = g_bnsum[c] / (double)NN;
    double var  = g_bnsum[96 + c] / (double)NN - mean*mean;
    float a = (float)((double)gam[c] / sqrt(var + 1e-5));
    g_bnab[c] = a;
    g_bnab[96 + c] = bet[c] - (float)mean * a;
}

__global__ void k_out(float* __restrict__ out) {
    int i = blockIdx.x*256 + threadIdx.x;
    if (i < NN*96) {
        int c = i % 96;
        float v = g_h[i] * g_bnab[c] + g_bnab[96 + c];
        out[i] = fmaxf(v, 0.f);
    }
}

// ---------------- launch ----------------
extern "C" void kernel_launch(void* const* d_in, const int* in_sizes, int n_in,
                              void* d_out, int out_size) {
    const float* x  = (const float*)d_in[0];
    const void*  ei = d_in[1];
    const float* w2 = (const float*)d_in[2];
    const float* b2 = (const float*)d_in[3];
    const float* w3 = (const float*)d_in[4];
    const float* b3 = (const float*)d_in[5];
    const float* w4 = (const float*)d_in[6];
    const float* b4 = (const float*)d_in[7];
    const float* aw = (const float*)d_in[8];
    const float* ab = (const float*)d_in[9];
    const float* fw = (const float*)d_in[10];
    const float* fb = (const float*)d_in[11];
    const float* gam = (const float*)d_in[12];
    const float* bet = (const float*)d_in[13];
    float* out = (float*)d_out;

    k_init<<<(NPAD*4 + 255)/256, 256>>>(ei);                 // 0
    k_decode_hist<<<(2*EE + 255)/256, 256>>>(ei);            // 1
    k_scan1<<<NB, 1024>>>();                                 // 2
    k_scan23<<<(NN + 255)/256, 256>>>();                     // 3
    k_scatter<<<(EE + 255)/256, 256>>>();                    // 4

    k_prop_csr<<<(NN*32 + 255)/256, 256>>>(x, 0);            // 5  (profiled)
    k_prop_csr<<<(NN*32 + 255)/256, 256>>>(x, 1);            // 6
    k_prop_csr<<<(NN*32 + 255)/256, 256>>>(x, 2);            // 7

    k_buildW<<<(384*288 + 255)/256, 256>>>(w2, b2, w3, b3, w4, b4);   // 8
    dim3 g1(3, NPAD/128);
    k_gemm1<<<g1, 256>>>(x, aw);                             // 9
    k_attn<<<(NN + 255)/256, 256>>>(ab);                     // 10
    dim3 g2(1, NPAD/128);
    k_gemm2<<<g2, 256>>>(fw, fb);                            // 11

    k_bnfin<<<1, 96>>>(gam, bet);                            // 12
    k_out<<<(NN*96 + 255)/256, 256>>>(out);                  // 13
}

// round 6
// speedup vs baseline: 2.1267x; 1.0124x over previous
#include <cuda_runtime.h>
#include <math.h>

#define NN   50000
#define NPAD 50048
#define CCH  96
#define EE   800000
#define NC   (NPAD*CCH)
#define NB   49          // scan blocks: 49*1024 >= 50000

// ---------------- device scratch ----------------
__device__ float  g_T1[NC];
__device__ float  g_T2[NC];
__device__ float  g_T3[NC];
__device__ float  g_concat[NPAD*288];
__device__ float  g_h[NC];
__device__ float  g_deg[NN];
__device__ float  g_dis[NN];
__device__ int    g_eidx[2*EE];
__device__ int    g_is64;
__device__ int    g_cnt[NN];
__device__ int    g_rowptr[NN+1];
__device__ int    g_cursor[NN];
__device__ int    g_bsum[NB];
__device__ int    g_csrc[EE];
__device__ float  g_cw[EE];
__device__ float  g_Wbig[384*288];
__device__ float  g_bcat[288];
__device__ float  g_logits[NPAD*4];
__device__ float  g_scalew[NPAD*4];
__device__ double g_bnsum[192];
__device__ float  g_bnab[192];

// ---------------- f32x2 helpers (sm_103a packed fp32) ----------------
__device__ __forceinline__ void ffma2(unsigned long long& d, unsigned long long a, unsigned long long b) {
    asm("fma.rn.f32x2 %0, %1, %2, %0;" : "+l"(d) : "l"(a), "l"(b));
}
__device__ __forceinline__ unsigned long long dupf(float v) {
    unsigned long long r; unsigned u = __float_as_uint(v);
    asm("mov.b64 %0, {%1,%1};" : "=l"(r) : "r"(u));
    return r;
}
__device__ __forceinline__ void unpack2(unsigned long long v, float& lo, float& hi) {
    unsigned a, b;
    asm("mov.b64 {%0,%1}, %2;" : "=r"(a), "=r"(b) : "l"(v));
    lo = __uint_as_float(a); hi = __uint_as_float(b);
}

// ---------------- init: zero counters + edge dtype detect ----------------
__global__ void k_init(const void* ei) {
    int i = blockIdx.x*256 + threadIdx.x;
    if (i < NN)  { g_deg[i] = 0.f; g_cnt[i] = 0; }
    if (i < 192) g_bnsum[i] = 0.0;
    if (i < NPAD*4) { g_logits[i] = 0.f; g_scalew[i] = 0.f; }
    if (blockIdx.x == 0) {
        __shared__ int any_nz;
        if (threadIdx.x == 0) any_nz = 0;
        __syncthreads();
        const int* p = (const int*)ei;
        int local = 0;
        for (int j = threadIdx.x; j < 4096; j += 256)
            if (p[2*j + 1] != 0) local = 1;
        if (local) atomicOr(&any_nz, 1);
        __syncthreads();
        if (threadIdx.x == 0) g_is64 = any_nz ? 0 : 1;
    }
}

// ---------------- decode + degree/count histogram ----------------
__global__ void k_decode_hist(const void* ei) {
    int e = blockIdx.x*256 + threadIdx.x;
    if (e >= 2*EE) return;
    int v;
    if (g_is64) v = (int)((const long long*)ei)[e];
    else        v = ((const int*)ei)[e];
    g_eidx[e] = v;
    if (e < EE) atomicAdd(&g_deg[v], 1.0f);
    else        atomicAdd(&g_cnt[v], 1);
}

// ---------------- prefix scan ----------------
__global__ void k_scan1() {
    __shared__ int s[1024];
    int tid = threadIdx.x;
    int i = blockIdx.x*1024 + tid;
    int v = (i < NN) ? g_cnt[i] : 0;
    s[tid] = v;
    __syncthreads();
    for (int off = 1; off < 1024; off <<= 1) {
        int t = (tid >= off) ? s[tid - off] : 0;
        __syncthreads();
        s[tid] += t;
        __syncthreads();
    }
    if (i < NN) g_rowptr[i] = s[tid] - v;   // exclusive within block
    if (tid == 1023) g_bsum[blockIdx.x] = s[tid];
}

// merged: block-offset add + cursor + dis
__global__ void k_scan23() {
    int i = blockIdx.x*256 + threadIdx.x;
    if (i == 0) g_rowptr[NN] = EE;
    if (i < NN) {
        int b = i >> 10;
        int off = 0;
        for (int k = 0; k < b; k++) off += g_bsum[k];
        int v = g_rowptr[i] + off;
        g_rowptr[i] = v;
        g_cursor[i] = v;
        float d = g_deg[i];
        g_dis[i] = (d > 0.f) ? rsqrtf(d) : 0.f;
    }
}

__global__ void k_scatter() {
    int e = blockIdx.x*256 + threadIdx.x;
    if (e >= EE) return;
    int r = g_eidx[e], c = g_eidx[EE + e];
    int pos = atomicAdd(&g_cursor[c], 1);
    g_csrc[pos] = r;
    g_cw[pos] = -g_dis[r] * g_dis[c];
}

// ---------------- CSR propagation: one warp per dst, 3 ch/lane, 8-edge unroll ----------------
// which=0: T1 = prop(x)
// which=1: T2 = 2*prop(T1) - x
// which=2: T3 = 2*prop(T2) - T1
__global__ void k_prop_csr(const float* __restrict__ x, int which) {
    const float* src; const float* sub; float* dst; float coef;
    if (which == 0)      { src = x;    sub = 0;    dst = g_T1; coef = 1.f; }
    else if (which == 1) { src = g_T1; sub = x;    dst = g_T2; coef = 2.f; }
    else                 { src = g_T2; sub = g_T1; dst = g_T3; coef = 2.f; }
    int w = (blockIdx.x*blockDim.x + threadIdx.x) >> 5;
    int lane = threadIdx.x & 31;
    if (w >= NN) return;
    int beg = g_rowptr[w], end = g_rowptr[w + 1];
    float a0 = 0.f, a1 = 0.f, a2 = 0.f;
    int i = beg;
    for (; i + 8 <= end; i += 8) {
        const float* sp[8];
        float ww[8];
        #pragma unroll
        for (int u = 0; u < 8; u++) {
            sp[u] = src + (size_t)g_csrc[i+u]*CCH;
            ww[u] = g_cw[i+u];
        }
        float p0[8], p1[8], p2[8];
        #pragma unroll
        for (int u = 0; u < 8; u++) {
            p0[u] = sp[u][lane];
            p1[u] = sp[u][lane+32];
            p2[u] = sp[u][lane+64];
        }
        #pragma unroll
        for (int u = 0; u < 8; u++) {
            a0 += ww[u]*p0[u];
            a1 += ww[u]*p1[u];
            a2 += ww[u]*p2[u];
        }
    }
    for (; i + 4 <= end; i += 4) {
        int   r0 = g_csrc[i],   r1 = g_csrc[i+1], r2 = g_csrc[i+2], r3 = g_csrc[i+3];
        float w0 = g_cw[i],     w1 = g_cw[i+1],   w2 = g_cw[i+2],   w3 = g_cw[i+3];
        const float* s0 = src + (size_t)r0*CCH;
        const float* s1 = src + (size_t)r1*CCH;
        const float* s2 = src + (size_t)r2*CCH;
        const float* s3 = src + (size_t)r3*CCH;
        float p00 = s0[lane], p01 = s0[lane+32], p02 = s0[lane+64];
        float p10 = s1[lane], p11 = s1[lane+32], p12 = s1[lane+64];
        float p20 = s2[lane], p21 = s2[lane+32], p22 = s2[lane+64];
        float p30 = s3[lane], p31 = s3[lane+32], p32 = s3[lane+64];
        a0 += w0*p00 + w1*p10 + w2*p20 + w3*p30;
        a1 += w0*p01 + w1*p11 + w2*p21 + w3*p31;
        a2 += w0*p02 + w1*p12 + w2*p22 + w3*p32;
    }
    for (; i < end; i++) {
        int r0 = g_csrc[i]; float w0 = g_cw[i];
        const float* s0 = src + (size_t)r0*CCH;
        a0 += w0*s0[lane]; a1 += w0*s0[lane+32]; a2 += w0*s0[lane+64];
    }
    float* dp = dst + (size_t)w*CCH;
    if (sub) {
        const float* sp = sub + (size_t)w*CCH;
        dp[lane]    = coef*a0 - sp[lane];
        dp[lane+32] = coef*a1 - sp[lane+32];
        dp[lane+64] = coef*a2 - sp[lane+64];
    } else {
        dp[lane] = a0; dp[lane+32] = a1; dp[lane+64] = a2;
    }
}

// ---------------- build block weight [384,288] + bias concat ----------------
__global__ void k_buildW(const float* __restrict__ w2, const float* __restrict__ b2,
                         const float* __restrict__ w3, const float* __restrict__ b3,
                         const float* __restrict__ w4, const float* __restrict__ b4) {
    int idx = blockIdx.x*256 + threadIdx.x;
    if (idx < 384*288) {
        int k = idx / 288, j = idx - k*288;
        int t = k / 96,  ki = k - t*96;
        int f = j / 96,  ji = j - f*96;
        const float* w = (f == 0) ? w2 : (f == 1) ? w3 : w4;
        int Kf = f + 2;
        g_Wbig[idx] = (t < Kf) ? w[(t*96 + ki)*96 + ji] : 0.f;
    }
    if (idx < 288) {
        int f = idx / 96, ji = idx - f*96;
        g_bcat[idx] = ((f == 0) ? b2 : (f == 1) ? b3 : b4)[ji];
    }
}

// ---------------- GEMM1 (one col block f): concat[:,f*96:+96] + attn-logit epilogue ----------------
// grid (NPAD/128); K = 96*(f+2)
__global__ void __launch_bounds__(256) k_gemm1(const float* __restrict__ x,
                                               const float* __restrict__ aw, int f) {
    __shared__ float AsT[16][138];
    __shared__ float Bs[16][96];
    int tid = threadIdx.x;
    int tx = tid & 15, ty = tid >> 4;
    int row0 = blockIdx.x * 128;
    int col0 = f*96;
    int K = 96*(f + 2);
    unsigned long long acc[4][6];
    #pragma unroll
    for (int r = 0; r < 4; r++)
        #pragma unroll
        for (int j = 0; j < 6; j++) acc[r][j] = 0ull;

    int arow = tid >> 1;
    int ak = (tid & 1) * 8;
    int grow = row0 + arow;

    for (int kb = 0; kb < K; kb += 16) {
        int sg = kb / 96;
        const float* base = (sg == 0) ? x : (sg == 1) ? g_T1 : (sg == 2) ? g_T2 : g_T3;
        int aoff = kb - sg*96;
        float4 v0 = make_float4(0.f,0.f,0.f,0.f), v1 = v0;
        if (grow < NN) {
            v0 = *(const float4*)(base + (size_t)grow*96 + aoff + ak);
            v1 = *(const float4*)(base + (size_t)grow*96 + aoff + ak + 4);
        }
        AsT[ak+0][arow] = v0.x; AsT[ak+1][arow] = v0.y;
        AsT[ak+2][arow] = v0.z; AsT[ak+3][arow] = v0.w;
        AsT[ak+4][arow] = v1.x; AsT[ak+5][arow] = v1.y;
        AsT[ak+6][arow] = v1.z; AsT[ak+7][arow] = v1.w;
        const float* Bp = g_Wbig + (size_t)kb*288 + col0;
        #pragma unroll
        for (int f2 = 0; f2 < 2; f2++) {
            int id = tid + f2*256;
            if (id < 384) {
                int r = id / 24, c = id - r*24;
                float4 v = *(const float4*)(Bp + (size_t)r*288 + c*4);
                *(float4*)&Bs[r][c*4] = v;
            }
        }
        __syncthreads();
        #pragma unroll
        for (int kk = 0; kk < 16; kk++) {
            unsigned long long a0 = *(const unsigned long long*)&AsT[kk][ty*8 + 0];
            unsigned long long a1 = *(const unsigned long long*)&AsT[kk][ty*8 + 2];
            unsigned long long a2 = *(const unsigned long long*)&AsT[kk][ty*8 + 4];
            unsigned long long a3 = *(const unsigned long long*)&AsT[kk][ty*8 + 6];
            float2 b01 = *(const float2*)&Bs[kk][tx*6];
            float2 b23 = *(const float2*)&Bs[kk][tx*6 + 2];
            float2 b45 = *(const float2*)&Bs[kk][tx*6 + 4];
            unsigned long long bb[6];
            bb[0] = dupf(b01.x); bb[1] = dupf(b01.y);
            bb[2] = dupf(b23.x); bb[3] = dupf(b23.y);
            bb[4] = dupf(b45.x); bb[5] = dupf(b45.y);
            #pragma unroll
            for (int j = 0; j < 6; j++) {
                ffma2(acc[0][j], a0, bb[j]);
                ffma2(acc[1][j], a1, bb[j]);
                ffma2(acc[2][j], a2, bb[j]);
                ffma2(acc[3][j], a3, bb[j]);
            }
        }
        __syncthreads();
    }
    // epilogue: write concat + accumulate attention logits (3 per row)
    float awr[3][6];
    #pragma unroll
    for (int j = 0; j < 6; j++) {
        int col = col0 + tx*6 + j;
        awr[0][j] = aw[col*3 + 0];
        awr[1][j] = aw[col*3 + 1];
        awr[2][j] = aw[col*3 + 2];
    }
    #pragma unroll
    for (int r = 0; r < 4; r++) {
        int rowe = row0 + ty*8 + 2*r;
        float lo[6], hi[6];
        #pragma unroll
        for (int j = 0; j < 6; j++) {
            float l_, h_;
            unpack2(acc[r][j], l_, h_);
            int col = col0 + tx*6 + j;
            float b = g_bcat[col];
            lo[j] = l_ + b; hi[j] = h_ + b;
            g_concat[(size_t)rowe*288 + col]     = lo[j];
            g_concat[(size_t)(rowe+1)*288 + col] = hi[j];
        }
        float ll0=0.f, ll1=0.f, ll2=0.f, lh0=0.f, lh1=0.f, lh2=0.f;
        #pragma unroll
        for (int j = 0; j < 6; j++) {
            ll0 += lo[j]*awr[0][j]; ll1 += lo[j]*awr[1][j]; ll2 += lo[j]*awr[2][j];
            lh0 += hi[j]*awr[0][j]; lh1 += hi[j]*awr[1][j]; lh2 += hi[j]*awr[2][j];
        }
        #pragma unroll
        for (int o = 1; o < 16; o <<= 1) {
            ll0 += __shfl_xor_sync(0xffffffffu, ll0, o);
            ll1 += __shfl_xor_sync(0xffffffffu, ll1, o);
            ll2 += __shfl_xor_sync(0xffffffffu, ll2, o);
            lh0 += __shfl_xor_sync(0xffffffffu, lh0, o);
            lh1 += __shfl_xor_sync(0xffffffffu, lh1, o);
            lh2 += __shfl_xor_sync(0xffffffffu, lh2, o);
        }
        if (tx == 0) {
            if (rowe < NN) {
                atomicAdd(&g_logits[rowe*4 + 0], ll0);
                atomicAdd(&g_logits[rowe*4 + 1], ll1);
                atomicAdd(&g_logits[rowe*4 + 2], ll2);
            }
            if (rowe + 1 < NN) {
                atomicAdd(&g_logits[(rowe+1)*4 + 0], lh0);
                atomicAdd(&g_logits[(rowe+1)*4 + 1], lh1);
                atomicAdd(&g_logits[(rowe+1)*4 + 2], lh2);
            }
        }
    }
}

// ---------------- attention: softmax over the 3 accumulated logits ----------------
__global__ void k_attn(const float* __restrict__ ab) {
    int n = blockIdx.x*256 + threadIdx.x;
    if (n >= NN) return;
    float l0 = g_logits[n*4 + 0] + ab[0];
    float l1 = g_logits[n*4 + 1] + ab[1];
    float l2 = g_logits[n*4 + 2] + ab[2];
    float m  = fmaxf(l0, fmaxf(l1, l2));
    float e0 = expf(l0 - m), e1 = expf(l1 - m), e2 = expf(l2 - m);
    float inv = 1.f / (e0 + e1 + e2);
    g_scalew[n*4 + 0] = e0*inv;
    g_scalew[n*4 + 1] = e1*inv;
    g_scalew[n*4 + 2] = e2*inv;
}

// ---------------- GEMM2: h = (concat * scalew) @ fus_w + fb, + BN-stat epilogue ----------------
// grid (NPAD/128)
__global__ void __launch_bounds__(256) k_gemm2(const float* __restrict__ fw,
                                               const float* __restrict__ fb) {
    __shared__ float AsT[16][138];
    __shared__ float Bs[16][96];
    __shared__ float sh_s[96], sh_s2[96];
    int tid = threadIdx.x;
    if (tid < 96) { sh_s[tid] = 0.f; sh_s2[tid] = 0.f; }
    int tx = tid & 15, ty = tid >> 4;
    int row0 = blockIdx.x * 128;
    unsigned long long acc[4][6];
    #pragma unroll
    for (int r = 0; r < 4; r++)
        #pragma unroll
        for (int j = 0; j < 6; j++) acc[r][j] = 0ull;

    int arow = tid >> 1;
    int ak = (tid & 1) * 8;
    int grow = row0 + arow;

    for (int kb = 0; kb < 288; kb += 16) {
        int seg = kb / 96;
        float4 v0 = make_float4(0.f,0.f,0.f,0.f), v1 = v0;
        if (grow < NN) {
            float sc = g_scalew[grow*4 + seg];
            v0 = *(const float4*)(g_concat + (size_t)grow*288 + kb + ak);
            v1 = *(const float4*)(g_concat + (size_t)grow*288 + kb + ak + 4);
            v0.x *= sc; v0.y *= sc; v0.z *= sc; v0.w *= sc;
            v1.x *= sc; v1.y *= sc; v1.z *= sc; v1.w *= sc;
        }
        AsT[ak+0][arow] = v0.x; AsT[ak+1][arow] = v0.y;
        AsT[ak+2][arow] = v0.z; AsT[ak+3][arow] = v0.w;
        AsT[ak+4][arow] = v1.x; AsT[ak+5][arow] = v1.y;
        AsT[ak+6][arow] = v1.z; AsT[ak+7][arow] = v1.w;
        const float* Bp = fw + (size_t)kb*96;
        #pragma unroll
        for (int f2 = 0; f2 < 2; f2++) {
            int id = tid + f2*256;
            if (id < 384) {
                int r = id / 24, c = id - r*24;
                float4 v = *(const float4*)(Bp + (size_t)r*96 + c*4);
                *(float4*)&Bs[r][c*4] = v;
            }
        }
        __syncthreads();
        #pragma unroll
        for (int kk = 0; kk < 16; kk++) {
            unsigned long long a0 = *(const unsigned long long*)&AsT[kk][ty*8 + 0];
            unsigned long long a1 = *(const unsigned long long*)&AsT[kk][ty*8 + 2];
            unsigned long long a2 = *(const unsigned long long*)&AsT[kk][ty*8 + 4];
            unsigned long long a3 = *(const unsigned long long*)&AsT[kk][ty*8 + 6];
            float2 b01 = *(const float2*)&Bs[kk][tx*6];
            float2 b23 = *(const float2*)&Bs[kk][tx*6 + 2];
            float2 b45 = *(const float2*)&Bs[kk][tx*6 + 4];
            unsigned long long bb[6];
            bb[0] = dupf(b01.x); bb[1] = dupf(b01.y);
            bb[2] = dupf(b23.x); bb[3] = dupf(b23.y);
            bb[4] = dupf(b45.x); bb[5] = dupf(b45.y);
            #pragma unroll
            for (int j = 0; j < 6; j++) {
                ffma2(acc[0][j], a0, bb[j]);
                ffma2(acc[1][j], a1, bb[j]);
                ffma2(acc[2][j], a2, bb[j]);
                ffma2(acc[3][j], a3, bb[j]);
            }
        }
        __syncthreads();
    }
    // epilogue: write h + BN partial sums
    float scol[6], s2col[6];
    #pragma unroll
    for (int j = 0; j < 6; j++) { scol[j] = 0.f; s2col[j] = 0.f; }
    #pragma unroll
    for (int r = 0; r < 4; r++) {
        int rowe = row0 + ty*8 + 2*r;
        #pragma unroll
        for (int j = 0; j < 6; j++) {
            float l_, h_;
            unpack2(acc[r][j], l_, h_);
            int col = tx*6 + j;
            float b = fb[col];
            l_ += b; h_ += b;
            if (rowe < NN) {
                g_h[(size_t)rowe*96 + col] = l_;
                scol[j] += l_; s2col[j] += l_*l_;
            }
            if (rowe + 1 < NN) {
                g_h[(size_t)(rowe+1)*96 + col] = h_;
                scol[j] += h_; s2col[j] += h_*h_;
            }
        }
    }
    #pragma unroll
    for (int j = 0; j < 6; j++) {
        atomicAdd(&sh_s[tx*6 + j],  scol[j]);
        atomicAdd(&sh_s2[tx*6 + j], s2col[j]);
    }
    __syncthreads();
    if (tid < 96) {
        atomicAdd(&g_bnsum[tid],      (double)sh_s[tid]);
        atomicAdd(&g_bnsum[96 + tid], (double)sh_s2[tid]);
    }
}

// ---------------- batchnorm finalize + output ----------------
__global__ void k_bnfin(const float* __restrict__ gam, const float* __restrict__ bet) {
    int c = threadIdx.x;
    double mean = g_bnsum[c] / (double)NN;
    double var  = g_bnsum[96 + c] / (double)NN - mean*mean;
    float a = (float)((double)gam[c] / sqrt(var + 1e-5));
    g_bnab[c] = a;
    g_bnab[96 + c] = bet[c] - (float)mean * a;
}

__global__ void k_out(float* __restrict__ out) {
    int i = blockIdx.x*256 + threadIdx.x;
    if (i < NN*96) {
        int c = i % 96;
        float v = g_h[i] * g_bnab[c] + g_bnab[96 + c];
        out[i] = fmaxf(v, 0.f);
    }
}

// ---------------- launch (2-stream fork/join for prop/GEMM1 overlap) ----------------
extern "C" void kernel_launch(void* const* d_in, const int* in_sizes, int n_in,
                              void* d_out, int out_size) {
    const float* x  = (const float*)d_in[0];
    const void*  ei = d_in[1];
    const float* w2 = (const float*)d_in[2];
    const float* b2 = (const float*)d_in[3];
    const float* w3 = (const float*)d_in[4];
    const float* b3 = (const float*)d_in[5];
    const float* w4 = (const float*)d_in[6];
    const float* b4 = (const float*)d_in[7];
    const float* aw = (const float*)d_in[8];
    const float* ab = (const float*)d_in[9];
    const float* fw = (const float*)d_in[10];
    const float* fb = (const float*)d_in[11];
    const float* gam = (const float*)d_in[12];
    const float* bet = (const float*)d_in[13];
    float* out = (float*)d_out;

    static cudaStream_t s1 = 0;
    static cudaEvent_t ev0 = 0, ev1 = 0, ev2 = 0, evJ = 0;
    if (!s1) {
        cudaStreamCreateWithFlags(&s1, cudaStreamNonBlocking);
        cudaEventCreateWithFlags(&ev0, cudaEventDisableTiming);
        cudaEventCreateWithFlags(&ev1, cudaEventDisableTiming);
        cudaEventCreateWithFlags(&ev2, cudaEventDisableTiming);
        cudaEventCreateWithFlags(&evJ, cudaEventDisableTiming);
    }

    dim3 gg(NPAD/128);

    k_init<<<(NPAD*4 + 255)/256, 256>>>(ei);
    // fork side stream
    cudaEventRecord(ev0, 0);
    cudaStreamWaitEvent(s1, ev0, 0);
    k_buildW<<<(384*288 + 255)/256, 256, 0, s1>>>(w2, b2, w3, b3, w4, b4);

    k_decode_hist<<<(2*EE + 255)/256, 256>>>(ei);
    k_scan1<<<NB, 1024>>>();
    k_scan23<<<(NN + 255)/256, 256>>>();
    k_scatter<<<(EE + 255)/256, 256>>>();

    k_prop_csr<<<(NN*32 + 255)/256, 256>>>(x, 0);            // T1
    cudaEventRecord(ev1, 0);
    cudaStreamWaitEvent(s1, ev1, 0);
    k_gemm1<<<gg, 256, 0, s1>>>(x, aw, 0);                   // needs x,T1 — overlaps prop2

    k_prop_csr<<<(NN*32 + 255)/256, 256>>>(x, 1);            // T2
    cudaEventRecord(ev2, 0);
    cudaStreamWaitEvent(s1, ev2, 0);
    k_gemm1<<<gg, 256, 0, s1>>>(x, aw, 1);                   // needs T2 — overlaps prop3
    cudaEventRecord(evJ, s1);

    k_prop_csr<<<(NN*32 + 255)/256, 256>>>(x, 2);            // T3
    k_gemm1<<<gg, 256>>>(x, aw, 2);                          // needs T3, on main stream

    cudaStreamWaitEvent(0, evJ, 0);                          // join
    k_attn<<<(NN + 255)/256, 256>>>(ab);
    k_gemm2<<<gg, 256>>>(fw, fb);

    k_bnfin<<<1, 96>>>(gam, bet);
    k_out<<<(NN*96 + 255)/256, 256>>>(out);
}